// round 6
// baseline (speedup 1.0000x reference)
#include <cuda_runtime.h>

#define BB 8
#define LL 32768
#define DD 128
#define NTOK (BB * LL)
#define TILE 2048
#define NTILES (NTOK / TILE)
#define KTPB 64   // key kernel threads (tokens) per block

__device__ ulonglong2 g_items[NTOK];

__device__ __forceinline__ unsigned int fmono(float f) {
    unsigned int b = __float_as_uint(f);
    return (b & 0x80000000u) ? ~b : (b | 0x80000000u);
}

// ---------------------------------------------------------------------------
// Key kernel — rounding model (verified by R5 group test, candidate C_A):
//   per projection h: 4 interleaved accumulators a_u, u = j mod 4,
//   FMA accumulation in ascending j, final combine (a0+a1)+(a2+a3).
// One thread per token; row staged in smem (odd stride -> conflict-free).
// ---------------------------------------------------------------------------
__global__ void __launch_bounds__(KTPB) key_kernel(const float* __restrict__ pts,
                                                   const float* __restrict__ alpha) {
    __shared__ float sal[DD * 3];
    __shared__ float tile[KTPB][DD + 5];  // row stride 133 (odd)
    int tid = threadIdx.x;
    size_t base = (size_t)blockIdx.x * KTPB;

    for (int i = tid; i < DD * 3; i += KTPB) sal[i] = alpha[i];
    for (int idx = tid; idx < KTPB * DD; idx += KTPB) {
        int tok = idx >> 7, d = idx & (DD - 1);
        tile[tok][d] = pts[(base + tok) * DD + d];
    }
    __syncthreads();

    const float* p = tile[tid];
    int gtok = (int)base + tid;

    // norm: only breaks exact fp32 key ties (verified compatible in R5)
    float sq = 0.f;
#pragma unroll
    for (int j = 0; j < DD; j++) sq = __fmaf_rn(p[j], p[j], sq);
    float nrm = __fsqrt_rn(sq);

    float k[3];
#pragma unroll
    for (int h = 0; h < 3; h++) {
        float a0 = 0.f, a1 = 0.f, a2 = 0.f, a3 = 0.f;
#pragma unroll
        for (int j = 0; j < DD; j += 4) {
            a0 = __fmaf_rn(p[j + 0], sal[(j + 0) * 3 + h], a0);
            a1 = __fmaf_rn(p[j + 1], sal[(j + 1) * 3 + h], a1);
            a2 = __fmaf_rn(p[j + 2], sal[(j + 2) * 3 + h], a2);
            a3 = __fmaf_rn(p[j + 3], sal[(j + 3) * 3 + h], a3);
        }
        k[h] = __fadd_rn(__fadd_rn(a0, a1), __fadd_rn(a2, a3));
    }

    // key = (k0 + 2*k1) + 4*k2 (left fold; power-of-2 muls exact)
    float key = __fadd_rn(__fadd_rn(k[0], __fmul_rn(2.f, k[1])), __fmul_rn(4.f, k[2]));

    ulonglong2 it;
    it.x = ((unsigned long long)fmono(key) << 32) | (unsigned long long)fmono(nrm);
    it.y = (unsigned long long)(gtok & (LL - 1));
    g_items[gtok] = it;
}

// ---------------------------------------------------------------------------
// Bitonic sort (XOR formulation, per-batch ascending; items unique via index)
// ---------------------------------------------------------------------------
__device__ __forceinline__ bool item_gt(const ulonglong2& a, const ulonglong2& b) {
    return (a.x > b.x) || (a.x == b.x && a.y > b.y);
}

__global__ void __launch_bounds__(1024) bitonic_shared_first() {
    __shared__ ulonglong2 s[TILE];
    int base = blockIdx.x * TILE;
    int tid  = threadIdx.x;
    s[tid]        = g_items[base + tid];
    s[tid + 1024] = g_items[base + tid + 1024];
    __syncthreads();
    for (int k = 2; k <= TILE; k <<= 1) {
        for (int j = k >> 1; j > 0; j >>= 1) {
            int i = 2 * tid - (tid & (j - 1));
            int l = i + j;
            bool asc = ((((unsigned)(base + i)) & (LL - 1)) & (unsigned)k) == 0;
            ulonglong2 a = s[i], b = s[l];
            if (item_gt(a, b) == asc) { s[i] = b; s[l] = a; }
            __syncthreads();
        }
    }
    g_items[base + tid]        = s[tid];
    g_items[base + tid + 1024] = s[tid + 1024];
}

__global__ void bitonic_global(int k, int j) {
    int t = blockIdx.x * blockDim.x + threadIdx.x;
    if (t >= NTOK / 2) return;
    unsigned int i = 2u * t - (t & (unsigned)(j - 1));
    unsigned int l = i + (unsigned)j;
    bool asc = ((i & (LL - 1)) & (unsigned)k) == 0;
    ulonglong2 a = g_items[i], b = g_items[l];
    if (item_gt(a, b) == asc) { g_items[i] = b; g_items[l] = a; }
}

__global__ void __launch_bounds__(1024) bitonic_shared_merge(int k) {
    __shared__ ulonglong2 s[TILE];
    int base = blockIdx.x * TILE;
    int tid  = threadIdx.x;
    s[tid]        = g_items[base + tid];
    s[tid + 1024] = g_items[base + tid + 1024];
    __syncthreads();
    bool asc = ((((unsigned)base) & (LL - 1)) & (unsigned)k) == 0;
    for (int j = 1024; j > 0; j >>= 1) {
        int i = 2 * tid - (tid & (j - 1));
        int l = i + j;
        ulonglong2 a = s[i], b = s[l];
        if (item_gt(a, b) == asc) { s[i] = b; s[l] = a; }
        __syncthreads();
    }
    g_items[base + tid]        = s[tid];
    g_items[base + tid + 1024] = s[tid + 1024];
}

// ---------------------------------------------------------------------------
// Gather: one warp per output row (random 512B row reads, streaming writes)
// ---------------------------------------------------------------------------
__global__ void gather_kernel(const float* __restrict__ pts,
                              float* __restrict__ out, int write_idx) {
    int gwarp = (blockIdx.x * blockDim.x + threadIdx.x) >> 5;
    int lane  = threadIdx.x & 31;
    if (gwarp >= NTOK) return;
    int b = gwarp >> 15;
    unsigned long long v = g_items[gwarp].y;
    const float4* src = reinterpret_cast<const float4*>(
        pts + ((size_t)b * LL + (size_t)v) * DD);
    float4* dst = reinterpret_cast<float4*>(out + (size_t)gwarp * DD);
    dst[lane] = src[lane];
    if (write_idx && lane == 0) {
        out[(size_t)NTOK * DD + gwarp] = (float)v;
    }
}

extern "C" void kernel_launch(void* const* d_in, const int* in_sizes, int n_in,
                              void* d_out, int out_size) {
    (void)n_in;
    const float* pts   = (const float*)d_in[0];
    const float* alpha = (const float*)d_in[1];
    if (in_sizes[0] < in_sizes[1]) { pts = (const float*)d_in[1]; alpha = (const float*)d_in[0]; }

    float* out = (float*)d_out;
    int write_idx = (out_size >= NTOK * DD + NTOK) ? 1 : 0;

    key_kernel<<<NTOK / KTPB, KTPB>>>(pts, alpha);

    bitonic_shared_first<<<NTILES, 1024>>>();
    for (int k = 2 * TILE; k <= LL; k <<= 1) {
        for (int j = k >> 1; j >= TILE; j >>= 1) {
            bitonic_global<<<(NTOK / 2 + 255) / 256, 256>>>(k, j);
        }
        bitonic_shared_merge<<<NTILES, 1024>>>(k);
    }

    gather_kernel<<<NTOK / 8, 256>>>(pts, out, write_idx);
}

// round 7
// speedup vs baseline: 1.9202x; 1.9202x over previous
#include <cuda_runtime.h>

#define BB 8
#define LL 32768
#define DD 128
#define NTOK (BB * LL)
#define TILE 2048
#define NTILES (NTOK / TILE)

__device__ ulonglong2 g_items[NTOK];

__device__ __forceinline__ unsigned int fmono(float f) {
    unsigned int b = __float_as_uint(f);
    return (b & 0x80000000u) ? ~b : (b | 0x80000000u);
}
__device__ __forceinline__ bool item_gt(const ulonglong2& a, const ulonglong2& b) {
    return (a.x > b.x) || (a.x == b.x && a.y > b.y);
}
__device__ __forceinline__ ulonglong2 shfl_item(ulonglong2 v, int m) {
    ulonglong2 o;
    o.x = __shfl_xor_sync(0xffffffffu, v.x, m);
    o.y = __shfl_xor_sync(0xffffffffu, v.y, m);
    return o;
}

// ---------------------------------------------------------------------------
// Key kernel — rounding model LOCKED (R5/R6 verified bit-exact, candidate C_A):
//   per projection h: 4 interleaved accumulators a_u (u = d mod 4), FMA in
//   ascending d, final combine (a0+a1)+(a2+a3); key = (k0 + 2*k1) + 4*k2.
// Staging: 128 tokens/block, 32-dim chunks, float4 loads, stride-33 smem.
// ---------------------------------------------------------------------------
__global__ void __launch_bounds__(128) key_kernel(const float* __restrict__ pts,
                                                  const float* __restrict__ alpha) {
    __shared__ float sal[DD * 3];
    __shared__ float tile[128][33];
    int tid = threadIdx.x;
    size_t base = (size_t)blockIdx.x * 128;

    for (int i = tid; i < DD * 3; i += 128) sal[i] = alpha[i];

    float a[3][4];
#pragma unroll
    for (int h = 0; h < 3; h++)
#pragma unroll
        for (int u = 0; u < 4; u++) a[h][u] = 0.f;
    float sq = 0.f;

#pragma unroll
    for (int c = 0; c < 4; c++) {
        __syncthreads();  // covers sal on first pass, tile reuse after
        // load 128 tokens x 32 dims via float4 (coalesced)
#pragma unroll
        for (int q = tid; q < 1024; q += 128) {
            int tok = q >> 3, v = q & 7;
            float4 f = *reinterpret_cast<const float4*>(
                pts + (base + tok) * DD + c * 32 + v * 4);
            tile[tok][v * 4 + 0] = f.x;
            tile[tok][v * 4 + 1] = f.y;
            tile[tok][v * 4 + 2] = f.z;
            tile[tok][v * 4 + 3] = f.w;
        }
        __syncthreads();
        const float* p = tile[tid];
#pragma unroll
        for (int j = 0; j < 32; j += 4) {
            int d = c * 32 + j;
#pragma unroll
            for (int u = 0; u < 4; u++) {
                float pv = p[j + u];
                a[0][u] = __fmaf_rn(pv, sal[(d + u) * 3 + 0], a[0][u]);
                a[1][u] = __fmaf_rn(pv, sal[(d + u) * 3 + 1], a[1][u]);
                a[2][u] = __fmaf_rn(pv, sal[(d + u) * 3 + 2], a[2][u]);
                sq      = __fmaf_rn(pv, pv, sq);
            }
        }
    }

    float k0 = __fadd_rn(__fadd_rn(a[0][0], a[0][1]), __fadd_rn(a[0][2], a[0][3]));
    float k1 = __fadd_rn(__fadd_rn(a[1][0], a[1][1]), __fadd_rn(a[1][2], a[1][3]));
    float k2 = __fadd_rn(__fadd_rn(a[2][0], a[2][1]), __fadd_rn(a[2][2], a[2][3]));
    float key = __fadd_rn(__fadd_rn(k0, __fmul_rn(2.f, k1)), __fmul_rn(4.f, k2));
    float nrm = __fsqrt_rn(sq);

    int gtok = (int)base + tid;
    ulonglong2 it;
    it.x = ((unsigned long long)fmono(key) << 32) | (unsigned long long)fmono(nrm);
    it.y = (unsigned long long)(gtok & (LL - 1));
    g_items[gtok] = it;
}

// ---------------------------------------------------------------------------
// Stage 1: full bitonic sort of each 2048 tile. Strides j<=16 via warp
// shuffles (no barriers); j>=32 via smem.
// ---------------------------------------------------------------------------
__global__ void __launch_bounds__(1024) bitonic_shared_first() {
    __shared__ ulonglong2 s[TILE];
    int base = blockIdx.x * TILE;
    int tid  = threadIdx.x;
    ulonglong2 x = g_items[base + tid];
    ulonglong2 y = g_items[base + tid + 1024];

    // k = 2..32: entirely warp-local (asc same for x and y element indices)
#pragma unroll
    for (int k = 2; k <= 32; k <<= 1) {
        bool asc = (tid & k) == 0;
#pragma unroll
        for (int j = k >> 1; j; j >>= 1) {
            ulonglong2 ox = shfl_item(x, j), oy = shfl_item(y, j);
            bool wmin = ((tid & j) == 0) == asc;
            if (item_gt(x, ox) == wmin) x = ox;
            if (item_gt(y, oy) == wmin) y = oy;
        }
    }

    // k = 64..2048: smem for j>=32, shuffles for j<=16
    for (int k = 64; k <= TILE; k <<= 1) {
        s[tid] = x; s[tid + 1024] = y;
        __syncthreads();
        for (int j = k >> 1; j >= 32; j >>= 1) {
            int i = 2 * tid - (tid & (j - 1));
            int l = i + j;
            bool asc = (((unsigned)(base + i) & (LL - 1)) & (unsigned)k) == 0;
            ulonglong2 a = s[i], b = s[l];
            if (item_gt(a, b) == asc) { s[i] = b; s[l] = a; }
            __syncthreads();
        }
        x = s[tid]; y = s[tid + 1024];
        bool ascx = (((unsigned)(base + tid) & (LL - 1)) & (unsigned)k) == 0;
        bool ascy = (((unsigned)(base + tid + 1024) & (LL - 1)) & (unsigned)k) == 0;
#pragma unroll
        for (int j = 16; j; j >>= 1) {
            ulonglong2 ox = shfl_item(x, j), oy = shfl_item(y, j);
            bool wminx = ((tid & j) == 0) == ascx;
            bool wminy = ((tid & j) == 0) == ascy;
            if (item_gt(x, ox) == wminx) x = ox;
            if (item_gt(y, oy) == wminy) y = oy;
        }
    }
    g_items[base + tid] = x;
    g_items[base + tid + 1024] = y;
}

// ---------------------------------------------------------------------------
// Fused global pass for stage k: ALL strides >= 2048 (k/2 .. 2048) applied in
// registers. M = k/2048 elements per thread at stride 2048. Direction is
// uniform per group. Replaces k/4096 single-stride kernels.
// ---------------------------------------------------------------------------
template <int M>
__global__ void __launch_bounds__(256) bitonic_global_fused(int k) {
    int g = blockIdx.x * blockDim.x + threadIdx.x;  // group id, NTOK/M groups
    int high = g >> 11, low = g & 2047;
    unsigned base = (unsigned)high * (M * 2048) + (unsigned)low;

    ulonglong2 v[M];
#pragma unroll
    for (int t = 0; t < M; t++) v[t] = g_items[base + t * 2048];

    bool asc = ((base & (LL - 1)) & (unsigned)k) == 0;
#pragma unroll
    for (int s = M / 2; s; s >>= 1) {
#pragma unroll
        for (int t = 0; t < M; t++) {
            if (!(t & s)) {
                ulonglong2 a = v[t], b = v[t | s];
                if (item_gt(a, b) == asc) { v[t] = b; v[t | s] = a; }
            }
        }
    }
#pragma unroll
    for (int t = 0; t < M; t++) g_items[base + t * 2048] = v[t];
}

// ---------------------------------------------------------------------------
// Tile merge for stage k (k > TILE): uniform direction; j=1024..32 in smem,
// j<=16 via shuffles.
// ---------------------------------------------------------------------------
__global__ void __launch_bounds__(1024) bitonic_shared_merge(int k) {
    __shared__ ulonglong2 s[TILE];
    int base = blockIdx.x * TILE;
    int tid  = threadIdx.x;
    bool asc = (((unsigned)base & (LL - 1)) & (unsigned)k) == 0;

    s[tid]        = g_items[base + tid];
    s[tid + 1024] = g_items[base + tid + 1024];
    __syncthreads();
    for (int j = 1024; j >= 32; j >>= 1) {
        int i = 2 * tid - (tid & (j - 1));
        int l = i + j;
        ulonglong2 a = s[i], b = s[l];
        if (item_gt(a, b) == asc) { s[i] = b; s[l] = a; }
        __syncthreads();
    }
    ulonglong2 x = s[tid], y = s[tid + 1024];
#pragma unroll
    for (int j = 16; j; j >>= 1) {
        ulonglong2 ox = shfl_item(x, j), oy = shfl_item(y, j);
        bool wmin = ((tid & j) == 0) == asc;
        if (item_gt(x, ox) == wmin) x = ox;
        if (item_gt(y, oy) == wmin) y = oy;
    }
    g_items[base + tid]        = x;
    g_items[base + tid + 1024] = y;
}

// ---------------------------------------------------------------------------
// Gather: one warp per output row (coalesced 512B row read + streaming write)
// ---------------------------------------------------------------------------
__global__ void __launch_bounds__(256) gather_kernel(const float* __restrict__ pts,
                                                     float* __restrict__ out,
                                                     int write_idx) {
    int gwarp = (blockIdx.x * blockDim.x + threadIdx.x) >> 5;
    int lane  = threadIdx.x & 31;
    if (gwarp >= NTOK) return;
    int b = gwarp >> 15;
    unsigned long long v = g_items[gwarp].y;
    const float4* src = reinterpret_cast<const float4*>(
        pts + ((size_t)b * LL + (size_t)v) * DD);
    float4* dst = reinterpret_cast<float4*>(out + (size_t)gwarp * DD);
    dst[lane] = src[lane];
    if (write_idx && lane == 0) {
        out[(size_t)NTOK * DD + gwarp] = (float)v;
    }
}

extern "C" void kernel_launch(void* const* d_in, const int* in_sizes, int n_in,
                              void* d_out, int out_size) {
    (void)n_in;
    const float* pts   = (const float*)d_in[0];
    const float* alpha = (const float*)d_in[1];
    if (in_sizes[0] < in_sizes[1]) { pts = (const float*)d_in[1]; alpha = (const float*)d_in[0]; }

    float* out = (float*)d_out;
    int write_idx = (out_size >= NTOK * DD + NTOK) ? 1 : 0;

    key_kernel<<<NTOK / 128, 128>>>(pts, alpha);

    bitonic_shared_first<<<NTILES, 1024>>>();

    bitonic_global_fused<2><<<(NTOK / 2) / 256, 256>>>(4096);
    bitonic_shared_merge<<<NTILES, 1024>>>(4096);

    bitonic_global_fused<4><<<(NTOK / 4) / 256, 256>>>(8192);
    bitonic_shared_merge<<<NTILES, 1024>>>(8192);

    bitonic_global_fused<8><<<(NTOK / 8) / 256, 256>>>(16384);
    bitonic_shared_merge<<<NTILES, 1024>>>(16384);

    bitonic_global_fused<16><<<(NTOK / 16) / 256, 256>>>(32768);
    bitonic_shared_merge<<<NTILES, 1024>>>(32768);

    gather_kernel<<<NTOK / 8, 256>>>(pts, out, write_idx);
}

// round 8
// speedup vs baseline: 2.0435x; 1.0642x over previous
#include <cuda_runtime.h>

#define BB 8
#define LL 32768
#define DD 128
#define NTOK (BB * LL)
#define TILE 2048
#define NTILES (NTOK / TILE)

__device__ ulonglong2 g_items[NTOK];
__device__ int g_inv[NTOK];   // final position of each source row

__device__ __forceinline__ unsigned int fmono(float f) {
    unsigned int b = __float_as_uint(f);
    return (b & 0x80000000u) ? ~b : (b | 0x80000000u);
}
__device__ __forceinline__ bool item_gt(const ulonglong2& a, const ulonglong2& b) {
    return (a.x > b.x) || (a.x == b.x && a.y > b.y);
}
__device__ __forceinline__ void ce(ulonglong2& a, ulonglong2& b, bool asc) {
    if (item_gt(a, b) == asc) { ulonglong2 t = a; a = b; b = t; }
}
__device__ __forceinline__ ulonglong2 shfl_item(ulonglong2 v, int m) {
    ulonglong2 o;
    o.x = __shfl_xor_sync(0xffffffffu, v.x, m);
    o.y = __shfl_xor_sync(0xffffffffu, v.y, m);
    return o;
}

// ---------------------------------------------------------------------------
// Key kernel — rounding model LOCKED (R5/R6 verified bit-exact, candidate C_A):
//   per projection h: 4 interleaved accumulators a_u (u = d mod 4), FMA in
//   ascending d, final combine (a0+a1)+(a2+a3); key = (k0 + 2*k1) + 4*k2.
// ---------------------------------------------------------------------------
__global__ void __launch_bounds__(128) key_kernel(const float* __restrict__ pts,
                                                  const float* __restrict__ alpha) {
    __shared__ float sal[DD * 3];
    __shared__ float tile[128][33];
    int tid = threadIdx.x;
    size_t base = (size_t)blockIdx.x * 128;

    for (int i = tid; i < DD * 3; i += 128) sal[i] = alpha[i];

    float a[3][4];
#pragma unroll
    for (int h = 0; h < 3; h++)
#pragma unroll
        for (int u = 0; u < 4; u++) a[h][u] = 0.f;
    float sq = 0.f;

#pragma unroll
    for (int c = 0; c < 4; c++) {
        __syncthreads();
#pragma unroll
        for (int q = tid; q < 1024; q += 128) {
            int tok = q >> 3, v = q & 7;
            float4 f = *reinterpret_cast<const float4*>(
                pts + (base + tok) * DD + c * 32 + v * 4);
            tile[tok][v * 4 + 0] = f.x;
            tile[tok][v * 4 + 1] = f.y;
            tile[tok][v * 4 + 2] = f.z;
            tile[tok][v * 4 + 3] = f.w;
        }
        __syncthreads();
        const float* p = tile[tid];
#pragma unroll
        for (int j = 0; j < 32; j += 4) {
            int d = c * 32 + j;
#pragma unroll
            for (int u = 0; u < 4; u++) {
                float pv = p[j + u];
                a[0][u] = __fmaf_rn(pv, sal[(d + u) * 3 + 0], a[0][u]);
                a[1][u] = __fmaf_rn(pv, sal[(d + u) * 3 + 1], a[1][u]);
                a[2][u] = __fmaf_rn(pv, sal[(d + u) * 3 + 2], a[2][u]);
                sq      = __fmaf_rn(pv, pv, sq);
            }
        }
    }

    float k0 = __fadd_rn(__fadd_rn(a[0][0], a[0][1]), __fadd_rn(a[0][2], a[0][3]));
    float k1 = __fadd_rn(__fadd_rn(a[1][0], a[1][1]), __fadd_rn(a[1][2], a[1][3]));
    float k2 = __fadd_rn(__fadd_rn(a[2][0], a[2][1]), __fadd_rn(a[2][2], a[2][3]));
    float key = __fadd_rn(__fadd_rn(k0, __fmul_rn(2.f, k1)), __fmul_rn(4.f, k2));
    float nrm = __fsqrt_rn(sq);

    int gtok = (int)base + tid;
    ulonglong2 it;
    it.x = ((unsigned long long)fmono(key) << 32) | (unsigned long long)fmono(nrm);
    it.y = (unsigned long long)(gtok & (LL - 1));
    g_items[gtok] = it;
}

// ---------------------------------------------------------------------------
// Stage 1: full bitonic sort of each 2048 tile (k = 2..2048).
// ---------------------------------------------------------------------------
__global__ void __launch_bounds__(1024) bitonic_shared_first() {
    __shared__ ulonglong2 s[TILE];
    int base = blockIdx.x * TILE;
    int tid  = threadIdx.x;
    ulonglong2 x = g_items[base + tid];
    ulonglong2 y = g_items[base + tid + 1024];

#pragma unroll
    for (int k = 2; k <= 32; k <<= 1) {
        bool asc = (tid & k) == 0;
#pragma unroll
        for (int j = k >> 1; j; j >>= 1) {
            ulonglong2 ox = shfl_item(x, j), oy = shfl_item(y, j);
            bool wmin = ((tid & j) == 0) == asc;
            if (item_gt(x, ox) == wmin) x = ox;
            if (item_gt(y, oy) == wmin) y = oy;
        }
    }

    for (int k = 64; k <= TILE; k <<= 1) {
        s[tid] = x; s[tid + 1024] = y;
        __syncthreads();
        for (int j = k >> 1; j >= 32; j >>= 1) {
            int i = 2 * tid - (tid & (j - 1));
            int l = i + j;
            bool asc = (((unsigned)(base + i) & (LL - 1)) & (unsigned)k) == 0;
            ulonglong2 a = s[i], b = s[l];
            if (item_gt(a, b) == asc) { s[i] = b; s[l] = a; }
            __syncthreads();
        }
        x = s[tid]; y = s[tid + 1024];
        bool ascx = (((unsigned)(base + tid) & (LL - 1)) & (unsigned)k) == 0;
        bool ascy = (((unsigned)(base + tid + 1024) & (LL - 1)) & (unsigned)k) == 0;
#pragma unroll
        for (int j = 16; j; j >>= 1) {
            ulonglong2 ox = shfl_item(x, j), oy = shfl_item(y, j);
            bool wminx = ((tid & j) == 0) == ascx;
            bool wminy = ((tid & j) == 0) == ascy;
            if (item_gt(x, ox) == wminx) x = ox;
            if (item_gt(y, oy) == wminy) y = oy;
        }
    }
    g_items[base + tid] = x;
    g_items[base + tid + 1024] = y;
}

// ---------------------------------------------------------------------------
// Fused global pass for stage k: all strides >= 2048 in registers.
// ---------------------------------------------------------------------------
template <int M>
__global__ void __launch_bounds__(256) bitonic_global_fused(int k) {
    int g = blockIdx.x * blockDim.x + threadIdx.x;
    int high = g >> 11, low = g & 2047;
    unsigned base = (unsigned)high * (M * 2048) + (unsigned)low;

    ulonglong2 v[M];
#pragma unroll
    for (int t = 0; t < M; t++) v[t] = g_items[base + t * 2048];

    bool asc = ((base & (LL - 1)) & (unsigned)k) == 0;
#pragma unroll
    for (int s = M / 2; s; s >>= 1) {
#pragma unroll
        for (int t = 0; t < M; t++) {
            if (!(t & s)) ce(v[t], v[t | s], asc);
        }
    }
#pragma unroll
    for (int t = 0; t < M; t++) g_items[base + t * 2048] = v[t];
}

// ---------------------------------------------------------------------------
// Tile merge for stage k (k > TILE, uniform direction per tile).
// 512 threads x 4 elements: strides 1024,512 in registers; 256..32 in smem
// (4 barriers); 16..1 via shuffles. If write_inv: emit inverse permutation
// (final positions) instead of writing items back.
// ---------------------------------------------------------------------------
__global__ void __launch_bounds__(512) bitonic_shared_merge(int k, int write_inv) {
    __shared__ ulonglong2 s[TILE];
    int base = blockIdx.x * TILE;
    int t = threadIdx.x;
    bool asc = (((unsigned)base & (LL - 1)) & (unsigned)k) == 0;

    ulonglong2 v[4];
#pragma unroll
    for (int i = 0; i < 4; i++) v[i] = g_items[base + t + i * 512];

    // stride 1024 (s=2), stride 512 (s=1) in registers
    ce(v[0], v[2], asc); ce(v[1], v[3], asc);
    ce(v[0], v[1], asc); ce(v[2], v[3], asc);

#pragma unroll
    for (int i = 0; i < 4; i++) s[t + i * 512] = v[i];
    __syncthreads();

    for (int j = 256; j >= 32; j >>= 1) {
#pragma unroll
        for (int qq = 0; qq < 2; qq++) {
            int q = t + qq * 512;
            int i = 2 * q - (q & (j - 1));
            int l = i + j;
            ulonglong2 a = s[i], b = s[l];
            if (item_gt(a, b) == asc) { s[i] = b; s[l] = a; }
        }
        __syncthreads();
    }

    int w = t >> 5, l = t & 31;
#pragma unroll
    for (int c = 0; c < 4; c++) {
        int idx = w * 128 + c * 32 + l;
        ulonglong2 x = s[idx];
#pragma unroll
        for (int j = 16; j; j >>= 1) {
            ulonglong2 ox = shfl_item(x, j);
            bool wmin = ((l & j) == 0) == asc;
            if (item_gt(x, ox) == wmin) x = ox;
        }
        int e = base + idx;
        if (write_inv) {
            int b = e >> 15;
            g_inv[b * LL + (int)x.y] = e;   // source row -> final position
        } else {
            g_items[e] = x;
        }
    }
}

// ---------------------------------------------------------------------------
// Scatter: linear read of pts (streaming), random full-row write via g_inv.
// One warp per source row.
// ---------------------------------------------------------------------------
__global__ void __launch_bounds__(256) scatter_kernel(const float* __restrict__ pts,
                                                      float* __restrict__ out,
                                                      int write_idx) {
    int gwarp = (blockIdx.x * blockDim.x + threadIdx.x) >> 5;
    int lane  = threadIdx.x & 31;
    if (gwarp >= NTOK) return;
    int dst = g_inv[gwarp];  // same address across warp -> broadcast
    const float4* src = reinterpret_cast<const float4*>(pts + (size_t)gwarp * DD);
    float4* d = reinterpret_cast<float4*>(out + (size_t)dst * DD);
    d[lane] = src[lane];
    if (write_idx && lane == 0) {
        out[(size_t)NTOK * DD + dst] = (float)(gwarp & (LL - 1));
    }
}

extern "C" void kernel_launch(void* const* d_in, const int* in_sizes, int n_in,
                              void* d_out, int out_size) {
    (void)n_in;
    const float* pts   = (const float*)d_in[0];
    const float* alpha = (const float*)d_in[1];
    if (in_sizes[0] < in_sizes[1]) { pts = (const float*)d_in[1]; alpha = (const float*)d_in[0]; }

    float* out = (float*)d_out;
    int write_idx = (out_size >= NTOK * DD + NTOK) ? 1 : 0;

    key_kernel<<<NTOK / 128, 128>>>(pts, alpha);

    bitonic_shared_first<<<NTILES, 1024>>>();

    bitonic_global_fused<2><<<(NTOK / 2) / 256, 256>>>(4096);
    bitonic_shared_merge<<<NTILES, 512>>>(4096, 0);

    bitonic_global_fused<4><<<(NTOK / 4) / 256, 256>>>(8192);
    bitonic_shared_merge<<<NTILES, 512>>>(8192, 0);

    bitonic_global_fused<8><<<(NTOK / 8) / 256, 256>>>(16384);
    bitonic_shared_merge<<<NTILES, 512>>>(16384, 0);

    bitonic_global_fused<16><<<(NTOK / 16) / 256, 256>>>(32768);
    bitonic_shared_merge<<<NTILES, 512>>>(32768, 1);

    scatter_kernel<<<NTOK / 8, 256>>>(pts, out, write_idx);
}